// round 1
// baseline (speedup 1.0000x reference)
#include <cuda_runtime.h>
#include <cuda_bf16.h>

// Problem constants (fixed shapes per reference setup_inputs)
#define HH 96
#define WW 160
#define CC 100
#define CP 104          // channels padded to multiple of 8 (16B bf16 chunks)
#define hH 48
#define hW 80
#define MD 9
#define KD 19
#define K2 361          // 19*19 offsets

// Distance-kernel tiling
#define PR 2
#define PC 4
#define TROWS (PR + 2*MD)   // 20
#define TCOLS (PC + 2*MD)   // 22
#define TPITCH 28           // shared pitch in uint4 units -> conflict-free LDS.128 phases
#define NCH (CP/8)          // 13 channel chunks of 8 bf16

// Scratch (device globals; no allocation allowed)
__device__ __align__(16) __nv_bfloat16 g_x[hH*hW*CP];
__device__ __align__(16) __nv_bfloat16 g_y[hH*hW*CP];
__device__ float g_S[hH*hW*K2];   // (sigmoid(d)-0.5)*2 at half res, layout [pixel][k]

// ---------------------------------------------------------------------------
// Kernel A: 2x2 avg pool both embeddings, convert to bf16, pad channels to 104
// ---------------------------------------------------------------------------
__global__ void kern_down(const float* __restrict__ prev, const float* __restrict__ query) {
    int idx = blockIdx.x * blockDim.x + threadIdx.x;
    if (idx >= hH*hW*CP) return;
    int ch = idx % CP;
    int p  = idx / CP;
    int r = p / hW, c = p - r*hW;
    float xv = 0.f, yv = 0.f;
    if (ch < CC) {
        int b = ((2*r)*WW + 2*c)*CC + ch;
        xv = 0.25f*(query[b] + query[b+CC] + query[b+WW*CC] + query[b+WW*CC+CC]);
        yv = 0.25f*(prev[b]  + prev[b+CC]  + prev[b+WW*CC]  + prev[b+WW*CC+CC]);
    }
    g_x[idx] = __float2bfloat16(xv);
    g_y[idx] = __float2bfloat16(yv);
}

// ---------------------------------------------------------------------------
// Kernel B: local squared distances + sigmoid transform at half resolution.
// Block = 2x4 pixel tile x all 361 offsets. 256 threads: pix = tid&7, kgroup =
// tid>>3 (32 groups, <=12 k each). y neighborhood staged in SMEM per 8-channel
// chunk; bf16x2 accumulation (error << 1e-3 budget; sigmoid saturates).
// ---------------------------------------------------------------------------
__global__ __launch_bounds__(256) void kern_dist() {
    __shared__ __align__(16) uint4 ys[TROWS*TPITCH];

    int tid = threadIdx.x;
    int pix = tid & 7;
    int kg  = tid >> 3;          // 0..31
    int pr  = pix >> 2;          // 0..1
    int pc  = pix & 3;           // 0..3
    int r0 = blockIdx.y * PR;
    int c0 = blockIdx.x * PC;
    int r = r0 + pr, c = c0 + pc;

    int soff[12];
    #pragma unroll
    for (int j = 0; j < 12; j++) {
        int k = kg + 32*j;
        int dy = k / KD;
        int dx = k - dy*KD;
        soff[j] = (pr + dy)*TPITCH + (pc + dx);
    }
    __nv_bfloat162 acc[12];
    #pragma unroll
    for (int j = 0; j < 12; j++) acc[j] = __float2bfloat162_rn(0.f);

    const uint4* xg = reinterpret_cast<const uint4*>(&g_x[(r*hW + c)*CP]);

    for (int ci = 0; ci < NCH; ci++) {
        __syncthreads();
        // stage y tile (20 x 22 positions, 8 bf16 channels each)
        for (int i = tid; i < TROWS*TCOLS; i += 256) {
            int row = i / TCOLS, col = i - row*TCOLS;
            int gr = r0 - MD + row, gc = c0 - MD + col;
            uint4 v = make_uint4(0u,0u,0u,0u);
            if (gr >= 0 && gr < hH && gc >= 0 && gc < hW)
                v = *reinterpret_cast<const uint4*>(&g_y[(gr*hW + gc)*CP + ci*8]);
            ys[row*TPITCH + col] = v;
        }
        __syncthreads();

        uint4 xv = xg[ci];
        const __nv_bfloat162* x2 = reinterpret_cast<const __nv_bfloat162*>(&xv);
        #pragma unroll
        for (int j = 0; j < 12; j++) {
            if (kg + 32*j < K2) {
                uint4 yv = ys[soff[j]];
                const __nv_bfloat162* y2 = reinterpret_cast<const __nv_bfloat162*>(&yv);
                #pragma unroll
                for (int t = 0; t < 4; t++) {
                    __nv_bfloat162 d = __hsub2(x2[t], y2[t]);
                    acc[j] = __hfma2(d, d, acc[j]);
                }
            }
        }
    }

    #pragma unroll
    for (int j = 0; j < 12; j++) {
        int k = kg + 32*j;
        if (k < K2) {
            int dy = k / KD, dx = k - dy*KD;
            int sr = r + dy - MD, sc = c + dx - MD;
            float val;
            if (sr < 0 || sr >= hH || sc < 0 || sc >= hW) {
                val = 1.0f;   // PAD_VAL distance -> sigmoid saturates to exactly 1
            } else {
                float d = __low2float(acc[j]) + __high2float(acc[j]);
                float e = __expf(-d);
                val = (1.0f - e) / (1.0f + e);   // == (sigmoid(d)-0.5)*2
            }
            g_S[(r*hW + c)*K2 + k] = val;
        }
    }
}

// ---------------------------------------------------------------------------
// Kernel C: bilinear upsample (align_corners) + masked min over offsets.
// One warp per output pixel; lanes split k; shuffle-min reduce per object.
// ---------------------------------------------------------------------------
#define MAXN 8
__global__ __launch_bounds__(256) void kern_out(const int* __restrict__ labels,
                                                const int* __restrict__ gt,
                                                float* __restrict__ out, int n) {
    int wid  = blockIdx.x * 8 + (threadIdx.x >> 5);
    int lane = threadIdx.x & 31;
    int Y = wid / WW;
    int X = wid - Y*WW;

    const float sH = (float)(47.0/95.0);     // (hH-1)/(HH-1)
    const float sW = (float)(79.0/159.0);    // (hW-1)/(WW-1)
    float pH = (float)Y * sH;
    float pW = (float)X * sW;
    int loH = (int)floorf(pH); if (loH > hH-2) loH = hH-2;
    int loW = (int)floorf(pW); if (loW > hW-2) loW = hW-2;
    float fH = pH - (float)loH;
    float fW = pW - (float)loW;
    float w00 = (1.f-fH)*(1.f-fW), w01 = (1.f-fH)*fW;
    float w10 = fH*(1.f-fW),       w11 = fH*fW;

    const float* S00 = &g_S[(loH*hW + loW)*K2];
    const float* S01 = S00 + K2;
    const float* S10 = S00 + hW*K2;
    const float* S11 = S10 + K2;

    int gid[MAXN];
    #pragma unroll
    for (int nn = 0; nn < MAXN; nn++) gid[nn] = (nn < n) ? gt[nn] : 0x7fffffff;
    float mv[MAXN];
    #pragma unroll
    for (int nn = 0; nn < MAXN; nn++) mv[nn] = 1.0f;

    for (int k = lane; k < K2; k += 32) {
        int dy = k / KD, dx = k - dy*KD;
        int ly = Y + dy - MD, lx = X + dx - MD;
        if (ly >= 0 && ly < HH && lx >= 0 && lx < WW) {   // OOB mask is False
            int lbl = labels[ly*WW + lx];
            float dval = w00*S00[k] + w01*S01[k] + w10*S10[k] + w11*S11[k];
            #pragma unroll
            for (int nn = 0; nn < MAXN; nn++)
                if (nn < n && lbl == gid[nn]) mv[nn] = fminf(mv[nn], dval);
        }
    }
    #pragma unroll
    for (int nn = 0; nn < MAXN; nn++) {
        float v = mv[nn];
        #pragma unroll
        for (int o = 16; o; o >>= 1) v = fminf(v, __shfl_xor_sync(0xffffffffu, v, o));
        if (lane == 0 && nn < n) out[(Y*WW + X)*n + nn] = v;
    }
}

// ---------------------------------------------------------------------------
extern "C" void kernel_launch(void* const* d_in, const int* in_sizes, int n_in,
                              void* d_out, int out_size) {
    const float* prev   = (const float*)d_in[0];
    const float* query  = (const float*)d_in[1];
    const int*   labels = (const int*)d_in[2];
    const int*   gt     = (const int*)d_in[3];
    float* out = (float*)d_out;
    int n = out_size / (HH*WW);   // number of objects (3)

    kern_down<<<(hH*hW*CP + 255)/256, 256>>>(prev, query);
    dim3 gb(hW/PC, hH/PR);        // (20, 24) = 480 blocks
    kern_dist<<<gb, 256>>>();
    kern_out<<<(HH*WW)/8, 256>>>(labels, gt, out, n);
}

// round 2
// speedup vs baseline: 1.6122x; 1.6122x over previous
#include <cuda_runtime.h>
#include <cuda_bf16.h>

// Fixed shapes
#define HH 96
#define WW 160
#define CC 100
#define hH 48
#define hW 80
#define MD 9
#define KD 19
#define K2 361
#define K2P 364          // padded stride for float4-aligned S rows

// int8 path
#define CP8 112          // channels padded to 112 int8 (7 x 16B chunks)
#define NCH8 7
#define QSCALE 32.0f
#define QSCALE2_INV (1.0f/1024.0f)

// dist-kernel tiling
#define PR 2
#define PC 4
#define TROWS (PR + 2*MD)   // 20
#define TCOLS (PC + 2*MD)   // 22
#define TPITCH 28           // uint4 pitch -> conflict-free 8-lane LDS.128 phases

// scratch (device globals; allocation is forbidden)
__device__ __align__(16) signed char g_xq[hH*hW*CP8];
__device__ __align__(16) signed char g_yq[hH*hW*CP8];
__device__ int g_sxq[hH*hW];
__device__ int g_syq[hH*hW];
__device__ __align__(16) float g_S[hH*hW*K2P];

// ---------------------------------------------------------------------------
// Kernel A: 2x2 avg-pool + int8 quantize (scale 32) + per-pixel sum of squares.
// One warp per half-res pixel; lane handles 4 channels via float4 loads.
// ---------------------------------------------------------------------------
__global__ __launch_bounds__(256) void kern_down(const float* __restrict__ prev,
                                                 const float* __restrict__ query) {
    int pixel = blockIdx.x * 8 + (threadIdx.x >> 5);
    int lane  = threadIdx.x & 31;
    int r = pixel / hW, c = pixel - r*hW;
    int ch0 = lane * 4;

    float4 xs = make_float4(0.f,0.f,0.f,0.f);
    float4 ys = xs;
    if (lane < 25) {            // 25*4 = 100 channels
        int b = ((2*r)*WW + 2*c)*CC + ch0;
        const float4* q0 = (const float4*)&query[b];
        const float4* q1 = (const float4*)&query[b + CC];
        const float4* q2 = (const float4*)&query[b + WW*CC];
        const float4* q3 = (const float4*)&query[b + WW*CC + CC];
        float4 a0=*q0, a1=*q1, a2=*q2, a3=*q3;
        xs = make_float4(0.25f*(a0.x+a1.x+a2.x+a3.x), 0.25f*(a0.y+a1.y+a2.y+a3.y),
                         0.25f*(a0.z+a1.z+a2.z+a3.z), 0.25f*(a0.w+a1.w+a2.w+a3.w));
        const float4* p0 = (const float4*)&prev[b];
        const float4* p1 = (const float4*)&prev[b + CC];
        const float4* p2 = (const float4*)&prev[b + WW*CC];
        const float4* p3 = (const float4*)&prev[b + WW*CC + CC];
        float4 b0=*p0, b1=*p1, b2=*p2, b3=*p3;
        ys = make_float4(0.25f*(b0.x+b1.x+b2.x+b3.x), 0.25f*(b0.y+b1.y+b2.y+b3.y),
                         0.25f*(b0.z+b1.z+b2.z+b3.z), 0.25f*(b0.w+b1.w+b2.w+b3.w));
    }
    // quantize
    int qx[4], qy[4];
    float vx[4] = {xs.x, xs.y, xs.z, xs.w};
    float vy[4] = {ys.x, ys.y, ys.z, ys.w};
    int sx = 0, sy = 0;
    #pragma unroll
    for (int t = 0; t < 4; t++) {
        int a = __float2int_rn(vx[t] * QSCALE);
        a = max(-127, min(127, a));
        int b = __float2int_rn(vy[t] * QSCALE);
        b = max(-127, min(127, b));
        qx[t] = a; qy[t] = b;
        sx += a*a; sy += b*b;
    }
    if (lane < 28) {            // 28*4 = 112 bytes per pixel (lanes 25-27 write zeros)
        char4 cx = make_char4((char)qx[0],(char)qx[1],(char)qx[2],(char)qx[3]);
        char4 cy = make_char4((char)qy[0],(char)qy[1],(char)qy[2],(char)qy[3]);
        *(char4*)&g_xq[pixel*CP8 + ch0] = cx;
        *(char4*)&g_yq[pixel*CP8 + ch0] = cy;
    }
    sx = __reduce_add_sync(0xffffffffu, sx);
    sy = __reduce_add_sync(0xffffffffu, sy);
    if (lane == 0) { g_sxq[pixel] = sx; g_syq[pixel] = sy; }
}

// ---------------------------------------------------------------------------
// Kernel B: local distances via int8 dp4a.  Block = 2x4 pixel tile x 361 k.
// 256 threads: pix = tid&7, kgroup = tid>>3 (32 groups, <=12 k each).
// d = (Sx + Sy - 2*dot)/1024, exact in int32; then (sigmoid(d)-0.5)*2.
// ---------------------------------------------------------------------------
__global__ __launch_bounds__(256) void kern_dist() {
    __shared__ __align__(16) uint4 ys[TROWS*TPITCH];
    __shared__ int sy_s[TROWS*TCOLS];

    int tid = threadIdx.x;
    int pix = tid & 7;
    int kg  = tid >> 3;
    int pr  = pix >> 2, pc = pix & 3;
    int r0 = blockIdx.y * PR, c0 = blockIdx.x * PC;
    int r = r0 + pr, c = c0 + pc;

    int soff[12];
    #pragma unroll
    for (int j = 0; j < 12; j++) {
        int k = kg + 32*j;
        int dy = k / KD;
        int dx = k - dy*KD;
        soff[j] = (pr + dy)*TPITCH + (pc + dx);
    }
    int acc[12];
    #pragma unroll
    for (int j = 0; j < 12; j++) acc[j] = 0;

    const uint4* xg = reinterpret_cast<const uint4*>(&g_xq[(r*hW + c)*CP8]);

    #pragma unroll 1
    for (int ci = 0; ci < NCH8; ci++) {
        __syncthreads();
        for (int i = tid; i < TROWS*TCOLS; i += 256) {
            int row = i / TCOLS, col = i - row*TCOLS;
            int gr = r0 - MD + row, gc = c0 - MD + col;
            uint4 v = make_uint4(0u,0u,0u,0u);
            if (gr >= 0 && gr < hH && gc >= 0 && gc < hW)
                v = *reinterpret_cast<const uint4*>(&g_yq[(gr*hW + gc)*CP8 + ci*16]);
            ys[row*TPITCH + col] = v;
        }
        __syncthreads();

        uint4 xv = xg[ci];
        #pragma unroll
        for (int j = 0; j < 12; j++) {
            if (kg + 32*j < K2) {
                uint4 yv = ys[soff[j]];
                int a = acc[j];
                a = __dp4a((int)xv.x, (int)yv.x, a);
                a = __dp4a((int)xv.y, (int)yv.y, a);
                a = __dp4a((int)xv.z, (int)yv.z, a);
                a = __dp4a((int)xv.w, (int)yv.w, a);
                acc[j] = a;
            }
        }
    }

    // stage neighbor sum-of-squares
    __syncthreads();
    for (int i = tid; i < TROWS*TCOLS; i += 256) {
        int row = i / TCOLS, col = i - row*TCOLS;
        int gr = r0 - MD + row, gc = c0 - MD + col;
        sy_s[i] = (gr >= 0 && gr < hH && gc >= 0 && gc < hW) ? g_syq[gr*hW + gc] : 0;
    }
    __syncthreads();

    int sx = g_sxq[r*hW + c];
    float* Srow = &g_S[(r*hW + c)*K2P];
    #pragma unroll
    for (int j = 0; j < 12; j++) {
        int k = kg + 32*j;
        if (k < K2P) {
            float val = 1.0f;   // PAD / out-of-range -> saturated sigmoid
            if (k < K2) {
                int dy = k / KD, dx = k - dy*KD;
                int sr = r + dy - MD, sc = c + dx - MD;
                if (sr >= 0 && sr < hH && sc >= 0 && sc < hW) {
                    int di = sx + sy_s[(pr + dy)*TCOLS + (pc + dx)] - 2*acc[j];
                    float d = (float)di * QSCALE2_INV;
                    float e = __expf(-d);
                    val = (1.0f - e) / (1.0f + e);   // == (sigmoid(d)-0.5)*2
                }
            }
            Srow[k] = val;
        }
    }
}

// ---------------------------------------------------------------------------
// Kernel C: bilinear upsample (align_corners) + per-object masked min.
// Block = 8 consecutive output pixels (one warp each). Label window staged in
// SMEM with sentinel -1 (covers OOB -> mask false). float4 S loads.
// ---------------------------------------------------------------------------
#define LROWS KD           // 19
#define LCOLS (8 + 2*MD)   // 26
template<int N>
__global__ __launch_bounds__(256) void kern_out(const int* __restrict__ labels,
                                                const int* __restrict__ gt,
                                                float* __restrict__ out) {
    __shared__ int lab[LROWS*LCOLS];
    int tid  = threadIdx.x;
    int warp = tid >> 5;
    int lane = tid & 31;
    int wid = blockIdx.x * 8;          // first pixel of block (same row, WW%8==0)
    int Y = wid / WW;
    int Xbase = wid - Y*WW;

    // stage label window [Y-9..Y+9] x [Xbase-9..Xbase+16]
    for (int i = tid; i < LROWS*LCOLS; i += 256) {
        int row = i / LCOLS, col = i - row*LCOLS;
        int gr = Y - MD + row, gc = Xbase - MD + col;
        lab[i] = (gr >= 0 && gr < HH && gc >= 0 && gc < WW) ? labels[gr*WW + gc] : -1;
    }
    __syncthreads();

    int X = Xbase + warp;
    const float sH = (float)(47.0/95.0);
    const float sW = (float)(79.0/159.0);
    float pH = (float)Y * sH;
    float pW = (float)X * sW;
    int loH = (int)floorf(pH); if (loH > hH-2) loH = hH-2;
    int loW = (int)floorf(pW); if (loW > hW-2) loW = hW-2;
    float fH = pH - (float)loH;
    float fW = pW - (float)loW;
    float w00 = (1.f-fH)*(1.f-fW), w01 = (1.f-fH)*fW;
    float w10 = fH*(1.f-fW),       w11 = fH*fW;

    const float* S00 = &g_S[(loH*hW + loW)*K2P];
    const float* S01 = S00 + K2P;
    const float* S10 = S00 + hW*K2P;
    const float* S11 = S10 + K2P;

    int gid[N];
    #pragma unroll
    for (int nn = 0; nn < N; nn++) gid[nn] = gt[nn];
    float mv[N];
    #pragma unroll
    for (int nn = 0; nn < N; nn++) mv[nn] = 1.0f;

    #pragma unroll
    for (int j = 0; j < 3; j++) {
        int kb = 128*j + 4*lane;
        if (kb < K2) {
            float4 a = *(const float4*)&S00[kb];
            float4 b = *(const float4*)&S01[kb];
            float4 cc = *(const float4*)&S10[kb];
            float4 dd = *(const float4*)&S11[kb];
            float av[4] = {a.x,a.y,a.z,a.w};
            float bv[4] = {b.x,b.y,b.z,b.w};
            float cv[4] = {cc.x,cc.y,cc.z,cc.w};
            float dv[4] = {dd.x,dd.y,dd.z,dd.w};
            #pragma unroll
            for (int t = 0; t < 4; t++) {
                int k = kb + t;
                if (k < K2) {
                    int dy = k / KD, dx = k - dy*KD;
                    int lbl = lab[dy*LCOLS + warp + dx];
                    float dval = w00*av[t] + w01*bv[t] + w10*cv[t] + w11*dv[t];
                    #pragma unroll
                    for (int nn = 0; nn < N; nn++)
                        if (lbl == gid[nn]) mv[nn] = fminf(mv[nn], dval);
                }
            }
        }
    }
    #pragma unroll
    for (int nn = 0; nn < N; nn++) {
        float v = mv[nn];
        #pragma unroll
        for (int o = 16; o; o >>= 1) v = fminf(v, __shfl_xor_sync(0xffffffffu, v, o));
        if (lane == 0) out[(Y*WW + X)*N + nn] = v;
    }
}

// ---------------------------------------------------------------------------
extern "C" void kernel_launch(void* const* d_in, const int* in_sizes, int n_in,
                              void* d_out, int out_size) {
    const float* prev   = (const float*)d_in[0];
    const float* query  = (const float*)d_in[1];
    const int*   labels = (const int*)d_in[2];
    const int*   gt     = (const int*)d_in[3];
    float* out = (float*)d_out;
    int n = out_size / (HH*WW);

    kern_down<<<hH*hW/8, 256>>>(prev, query);
    dim3 gb(hW/PC, hH/PR);
    kern_dist<<<gb, 256>>>();
    int blocks = HH*WW/8;
    switch (n) {
        case 1: kern_out<1><<<blocks,256>>>(labels, gt, out); break;
        case 2: kern_out<2><<<blocks,256>>>(labels, gt, out); break;
        case 3: kern_out<3><<<blocks,256>>>(labels, gt, out); break;
        case 4: kern_out<4><<<blocks,256>>>(labels, gt, out); break;
        case 5: kern_out<5><<<blocks,256>>>(labels, gt, out); break;
        case 6: kern_out<6><<<blocks,256>>>(labels, gt, out); break;
        case 7: kern_out<7><<<blocks,256>>>(labels, gt, out); break;
        default: kern_out<8><<<blocks,256>>>(labels, gt, out); break;
    }
}